// round 1
// baseline (speedup 1.0000x reference)
#include <cuda_runtime.h>
#include <math.h>

// Problem constants
#define B_  1024
#define D_  512
#define K_  256
#define J_  1024   // 2*D reduction length

// Scratch in device globals (no allocations allowed)
__device__ float g_U[B_ * J_];   // [b][j]: j<512 -> x^2, j>=512 -> x
__device__ float g_V[K_ * J_];   // [k][j]: j<512 -> 0.5*s2, j>=512 -> -m*s2
__device__ float g_C[K_];        // 0.5 * sum_d m^2 s2

// ---------------------------------------------------------------------------
// Prep 1: build V and C from (means, rho). One block per k.
// ---------------------------------------------------------------------------
__global__ __launch_bounds__(256) void prep_V_kernel(const float* __restrict__ means,
                                                     const float* __restrict__ rho) {
    const int k = blockIdx.x;
    const int t = threadIdx.x;
    __shared__ float red[256];

    float csum = 0.0f;
    for (int d = t; d < D_; d += 256) {
        float m = means[k * D_ + d];
        float r = rho[k * D_ + d];
        float s  = log1pf(expf(r));   // softplus, matches reference
        float s2 = s * s;
        g_V[k * J_ + d]        = 0.5f * s2;
        g_V[k * J_ + D_ + d]   = -m * s2;
        csum += 0.5f * m * m * s2;
    }
    red[t] = csum;
    __syncthreads();
    #pragma unroll
    for (int off = 128; off > 0; off >>= 1) {
        if (t < off) red[t] += red[t + off];
        __syncthreads();
    }
    if (t == 0) g_C[k] = red[0];
}

// ---------------------------------------------------------------------------
// Prep 2: build U from x (elementwise).
// ---------------------------------------------------------------------------
__global__ __launch_bounds__(256) void prep_U_kernel(const float* __restrict__ x) {
    const int i = blockIdx.x * 256 + threadIdx.x;   // over B*D
    if (i >= B_ * D_) return;
    const int b = i / D_;
    const int d = i % D_;
    float v = x[i];
    g_U[b * J_ + d]       = v * v;
    g_U[b * J_ + D_ + d]  = v;
}

// ---------------------------------------------------------------------------
// GEMM: out[b,k] = sum_j U[b,j]*V[k,j] + C[k]
// Tiles: BM=64 (b), BN=32 (k), BK=64 (j). 256 threads, 4x2 microtile.
// Grid: (1024/64) x (256/32) = 16 x 8 = 128 blocks.
// ---------------------------------------------------------------------------
#define BM 64
#define BN 32
#define BK 64

__global__ __launch_bounds__(256, 2) void gemm_kernel(float* __restrict__ out) {
    const int m0 = blockIdx.x * BM;
    const int n0 = blockIdx.y * BN;

    // Pads chosen so micro-loop LDS reads are (near) conflict-free and the
    // A-tile 128-bit stores stay 16B aligned (68*4 = 272 = 16*17).
    __shared__ float As[BM][BK + 4];   // [m][j]
    __shared__ float Bs[BN][BK + 1];   // [n][j]

    const int tid = threadIdx.x;
    const int tn = tid & 15;   // 0..15 -> 2 n's each
    const int tm = tid >> 4;   // 0..15 -> 4 m's each

    float acc[4][2] = {};

    for (int k0 = 0; k0 < J_; k0 += BK) {
        // Load A tile: 64 rows x 16 float4 = 1024 vecs, 4 per thread.
        #pragma unroll
        for (int v = 0; v < 4; v++) {
            int idx = tid + v * 256;
            int m  = idx >> 4;
            int kc = idx & 15;
            float4 tv = *reinterpret_cast<const float4*>(&g_U[(m0 + m) * J_ + k0 + kc * 4]);
            *reinterpret_cast<float4*>(&As[m][kc * 4]) = tv;
        }
        // Load B tile: 32 rows x 16 float4 = 512 vecs, 2 per thread.
        #pragma unroll
        for (int v = 0; v < 2; v++) {
            int idx = tid + v * 256;
            int n  = idx >> 4;
            int kc = idx & 15;
            float4 tv = *reinterpret_cast<const float4*>(&g_V[(n0 + n) * J_ + k0 + kc * 4]);
            Bs[n][kc * 4 + 0] = tv.x;
            Bs[n][kc * 4 + 1] = tv.y;
            Bs[n][kc * 4 + 2] = tv.z;
            Bs[n][kc * 4 + 3] = tv.w;
        }
        __syncthreads();

        #pragma unroll 16
        for (int kk = 0; kk < BK; kk++) {
            float a0 = As[tm * 4 + 0][kk];
            float a1 = As[tm * 4 + 1][kk];
            float a2 = As[tm * 4 + 2][kk];
            float a3 = As[tm * 4 + 3][kk];
            float b0 = Bs[tn * 2 + 0][kk];
            float b1 = Bs[tn * 2 + 1][kk];
            acc[0][0] += a0 * b0;  acc[0][1] += a0 * b1;
            acc[1][0] += a1 * b0;  acc[1][1] += a1 * b1;
            acc[2][0] += a2 * b0;  acc[2][1] += a2 * b1;
            acc[3][0] += a3 * b0;  acc[3][1] += a3 * b1;
        }
        __syncthreads();
    }

    const float c0 = g_C[n0 + tn * 2 + 0];
    const float c1 = g_C[n0 + tn * 2 + 1];
    #pragma unroll
    for (int i = 0; i < 4; i++) {
        int b = m0 + tm * 4 + i;
        float2 r;
        r.x = acc[i][0] + c0;
        r.y = acc[i][1] + c1;
        *reinterpret_cast<float2*>(&out[b * K_ + n0 + tn * 2]) = r;
    }
}

// ---------------------------------------------------------------------------
// Launch
// ---------------------------------------------------------------------------
extern "C" void kernel_launch(void* const* d_in, const int* in_sizes, int n_in,
                              void* d_out, int out_size) {
    const float* x     = (const float*)d_in[0];   // (1024, 512)
    const float* means = (const float*)d_in[1];   // (256, 1, 512)
    const float* rho   = (const float*)d_in[2];   // (256, 1, 512)
    float* out = (float*)d_out;                   // (1024, 256)

    prep_V_kernel<<<K_, 256>>>(means, rho);
    prep_U_kernel<<<(B_ * D_ + 255) / 256, 256>>>(x);
    gemm_kernel<<<dim3(B_ / BM, K_ / BN), 256>>>(out);
}

// round 3
// speedup vs baseline: 2.2315x; 2.2315x over previous
#include <cuda_runtime.h>
#include <cuda_bf16.h>
#include <cstdint>
#include <math.h>

#define B_ 1024
#define D_ 512
#define K_ 256
#define J_ 1024   // reduction length: [x^2 | x]

// ---------------- scratch (no allocations allowed) ----------------
__device__ __nv_bfloat16 g_Ahi[B_ * J_];
__device__ __nv_bfloat16 g_Alo[B_ * J_];
__device__ __nv_bfloat16 g_Bhi[K_ * J_];
__device__ __nv_bfloat16 g_Blo[K_ * J_];
__device__ float g_C[K_];

__device__ __forceinline__ uint32_t smem_u32(const void* p) {
    uint32_t a;
    asm("{ .reg .u64 t; cvta.to.shared.u64 t, %1; cvt.u32.u64 %0, t; }" : "=r"(a) : "l"(p));
    return a;
}
__device__ __forceinline__ void cpasync16(uint32_t dst, const void* src) {
    asm volatile("cp.async.cg.shared.global [%0], [%1], 16;\n" :: "r"(dst), "l"(src) : "memory");
}

// ---------------------------------------------------------------------------
// Fused prep.
//  blocks [0, 512): U rows from x, 4 elems (1 float4) per thread.
//  blocks [512, 544): V rows; one warp per k (8 warps/block), warp-shfl C.
// ---------------------------------------------------------------------------
#define NB_U 512

__global__ __launch_bounds__(256) void prep_kernel(const float* __restrict__ x,
                                                   const float* __restrict__ means,
                                                   const float* __restrict__ rho) {
    const int blk = blockIdx.x;
    const int tid = threadIdx.x;
    if (blk < NB_U) {
        const int idx = blk * 256 + tid;           // float4 index over B*D/4
        const int b = idx >> 7;                    // 128 float4 per row of x
        const int d = (idx & 127) * 4;
        float4 xv = ((const float4*)x)[idx];
        float vsq[4] = {xv.x * xv.x, xv.y * xv.y, xv.z * xv.z, xv.w * xv.w};
        float vx[4]  = {xv.x, xv.y, xv.z, xv.w};
        __nv_bfloat16 hsq[4], lsq[4], hx[4], lx[4];
        #pragma unroll
        for (int i = 0; i < 4; i++) {
            hsq[i] = __float2bfloat16(vsq[i]);
            lsq[i] = __float2bfloat16(vsq[i] - __bfloat162float(hsq[i]));
            hx[i]  = __float2bfloat16(vx[i]);
            lx[i]  = __float2bfloat16(vx[i] - __bfloat162float(hx[i]));
        }
        size_t base = (size_t)b * J_ + d;
        *(__nv_bfloat162*)&g_Ahi[base]          = __halves2bfloat162(hsq[0], hsq[1]);
        *(__nv_bfloat162*)&g_Ahi[base + 2]      = __halves2bfloat162(hsq[2], hsq[3]);
        *(__nv_bfloat162*)&g_Alo[base]          = __halves2bfloat162(lsq[0], lsq[1]);
        *(__nv_bfloat162*)&g_Alo[base + 2]      = __halves2bfloat162(lsq[2], lsq[3]);
        *(__nv_bfloat162*)&g_Ahi[base + D_]     = __halves2bfloat162(hx[0], hx[1]);
        *(__nv_bfloat162*)&g_Ahi[base + D_ + 2] = __halves2bfloat162(hx[2], hx[3]);
        *(__nv_bfloat162*)&g_Alo[base + D_]     = __halves2bfloat162(lx[0], lx[1]);
        *(__nv_bfloat162*)&g_Alo[base + D_ + 2] = __halves2bfloat162(lx[2], lx[3]);
    } else {
        const int wid = tid >> 5, lane = tid & 31;
        const int k = (blk - NB_U) * 8 + wid;      // 32 blocks x 8 warps = 256 k's
        const float4* mrow = (const float4*)(means + (size_t)k * D_);
        const float4* rrow = (const float4*)(rho   + (size_t)k * D_);
        float csum = 0.0f;
        #pragma unroll
        for (int i = 0; i < 4; i++) {
            int d4 = lane + i * 32;                // float4 index 0..127
            float4 m = mrow[d4];
            float4 r = rrow[d4];
            float mm[4] = {m.x, m.y, m.z, m.w};
            float rr[4] = {r.x, r.y, r.z, r.w};
            __nv_bfloat16 h0[4], l0[4], h1[4], l1[4];
            #pragma unroll
            for (int c = 0; c < 4; c++) {
                float s  = __logf(1.0f + __expf(rr[c]));   // softplus (fast, ~1e-7 rel)
                float s2 = s * s;
                float v0 = 0.5f * s2;
                float v1 = -mm[c] * s2;
                h0[c] = __float2bfloat16(v0);
                l0[c] = __float2bfloat16(v0 - __bfloat162float(h0[c]));
                h1[c] = __float2bfloat16(v1);
                l1[c] = __float2bfloat16(v1 - __bfloat162float(h1[c]));
                csum += 0.5f * mm[c] * mm[c] * s2;
            }
            size_t base = (size_t)k * J_ + d4 * 4;
            *(__nv_bfloat162*)&g_Bhi[base]          = __halves2bfloat162(h0[0], h0[1]);
            *(__nv_bfloat162*)&g_Bhi[base + 2]      = __halves2bfloat162(h0[2], h0[3]);
            *(__nv_bfloat162*)&g_Blo[base]          = __halves2bfloat162(l0[0], l0[1]);
            *(__nv_bfloat162*)&g_Blo[base + 2]      = __halves2bfloat162(l0[2], l0[3]);
            *(__nv_bfloat162*)&g_Bhi[base + D_]     = __halves2bfloat162(h1[0], h1[1]);
            *(__nv_bfloat162*)&g_Bhi[base + D_ + 2] = __halves2bfloat162(h1[2], h1[3]);
            *(__nv_bfloat162*)&g_Blo[base + D_]     = __halves2bfloat162(l1[0], l1[1]);
            *(__nv_bfloat162*)&g_Blo[base + D_ + 2] = __halves2bfloat162(l1[2], l1[3]);
        }
        #pragma unroll
        for (int off = 16; off > 0; off >>= 1)
            csum += __shfl_xor_sync(0xFFFFFFFFu, csum, off);
        if (lane == 0) g_C[k] = csum;
    }
}

// ---------------------------------------------------------------------------
// HMMA GEMM: out[1024,256] = U*V^T + C.
// BM=64, BN=32, KC=128 bf16 per stage, double-buffered cp.async.
// 256 threads = 8 warps as 4(M) x 2(N); warp tile 16x16.
// Split product: acc += Ahi*Bhi + Ahi*Blo + Alo*Bhi.
// ---------------------------------------------------------------------------
#define BM 64
#define BN 32
#define KC 128
#define NSTAGE (J_ / KC)          // 8
#define ROWB 272                  // (128 + 8 pad) bf16 = 272 bytes, conflict-free ldmatrix
#define OFF_AH 0
#define OFF_AL (BM * ROWB)                    // 17408
#define OFF_BH (2 * BM * ROWB)                // 34816
#define OFF_BL (2 * BM * ROWB + BN * ROWB)    // 43520
#define STAGE_BYTES (2 * BM * ROWB + 2 * BN * ROWB)   // 52224

__device__ __forceinline__ void ldm4(uint32_t* f, uint32_t addr) {
    asm volatile("ldmatrix.sync.aligned.m8n8.x4.shared.b16 {%0,%1,%2,%3}, [%4];"
                 : "=r"(f[0]), "=r"(f[1]), "=r"(f[2]), "=r"(f[3]) : "r"(addr));
}
__device__ __forceinline__ void mma16816(float* c, const uint32_t* a, uint32_t b0, uint32_t b1) {
    asm volatile("mma.sync.aligned.m16n8k16.row.col.f32.bf16.bf16.f32 "
                 "{%0,%1,%2,%3}, {%4,%5,%6,%7}, {%8,%9}, {%0,%1,%2,%3};"
                 : "+f"(c[0]), "+f"(c[1]), "+f"(c[2]), "+f"(c[3])
                 : "r"(a[0]), "r"(a[1]), "r"(a[2]), "r"(a[3]), "r"(b0), "r"(b1));
}

__device__ __forceinline__ void load_stage(uint32_t sb, int m0, int n0, int kelem, int tid) {
    const char* baseAh = (const char*)g_Ahi;
    const char* baseAl = (const char*)g_Alo;
    const char* baseBh = (const char*)g_Bhi;
    const char* baseBl = (const char*)g_Blo;
    const size_t kb = (size_t)kelem * 2;   // byte offset within a row
    #pragma unroll
    for (int i = 0; i < 4; i++) {          // A: 64 rows x 16 chunks = 1024
        int idx = tid + i * 256;
        int r = idx >> 4, c = idx & 15;
        uint32_t so = (uint32_t)(r * ROWB + c * 16);
        size_t go = (size_t)(m0 + r) * 2048 + kb + c * 16;
        cpasync16(sb + OFF_AH + so, baseAh + go);
        cpasync16(sb + OFF_AL + so, baseAl + go);
    }
    #pragma unroll
    for (int i = 0; i < 2; i++) {          // B: 32 rows x 16 chunks = 512
        int idx = tid + i * 256;
        int r = idx >> 4, c = idx & 15;
        uint32_t so = (uint32_t)(r * ROWB + c * 16);
        size_t go = (size_t)(n0 + r) * 2048 + kb + c * 16;
        cpasync16(sb + OFF_BH + so, baseBh + go);
        cpasync16(sb + OFF_BL + so, baseBl + go);
    }
    asm volatile("cp.async.commit_group;\n" ::: "memory");
}

__global__ __launch_bounds__(256) void gemm_kernel(float* __restrict__ out) {
    extern __shared__ char dyn[];
    __shared__ float Cs[BN];

    const int tid = threadIdx.x;
    const int wid = tid >> 5, lane = tid & 31;
    const int m0 = blockIdx.x * BM;
    const int n0 = blockIdx.y * BN;
    const int mw = (wid & 3) * 16;         // warp M offset
    const int nw = (wid >> 2) * 16;        // warp N offset

    const uint32_t sbase = smem_u32(dyn);

    load_stage(sbase, m0, n0, 0, tid);
    if (tid < BN) Cs[tid] = g_C[n0 + tid];

    float acc0[4] = {0.f, 0.f, 0.f, 0.f};  // n-tile 0 (cols nw..nw+7)
    float acc1[4] = {0.f, 0.f, 0.f, 0.f};  // n-tile 1 (cols nw+8..nw+15)

    // Precompute ldmatrix lane-address components (byte offsets within stage)
    const uint32_t aRow = (uint32_t)((mw + (lane & 15)) * ROWB);
    const uint32_t aCol = (uint32_t)(((lane >> 4) << 3) * 2);
    const uint32_t bRow = (uint32_t)((nw + (lane & 7) + ((lane >> 4) << 3)) * ROWB);
    const uint32_t bCol = (uint32_t)((((lane >> 3) & 1) << 3) * 2);

    for (int s = 0; s < NSTAGE; s++) {
        if (s + 1 < NSTAGE) {
            load_stage(sbase + ((s + 1) & 1) * STAGE_BYTES, m0, n0, (s + 1) * KC, tid);
            asm volatile("cp.async.wait_group 1;\n" ::: "memory");
        } else {
            asm volatile("cp.async.wait_group 0;\n" ::: "memory");
        }
        __syncthreads();

        const uint32_t sb = sbase + (s & 1) * STAGE_BYTES;
        #pragma unroll
        for (int kk = 0; kk < KC / 16; kk++) {
            const uint32_t kb = (uint32_t)(kk * 32);   // 16 bf16 = 32 bytes
            uint32_t aH[4], aL[4], bH[4], bL[4];
            ldm4(aH, sb + OFF_AH + aRow + aCol + kb);
            ldm4(aL, sb + OFF_AL + aRow + aCol + kb);
            ldm4(bH, sb + OFF_BH + bRow + bCol + kb);
            ldm4(bL, sb + OFF_BL + bRow + bCol + kb);
            mma16816(acc0, aH, bH[0], bH[1]);
            mma16816(acc1, aH, bH[2], bH[3]);
            mma16816(acc0, aH, bL[0], bL[1]);
            mma16816(acc1, aH, bL[2], bL[3]);
            mma16816(acc0, aL, bH[0], bH[1]);
            mma16816(acc1, aL, bH[2], bH[3]);
        }
        __syncthreads();
    }

    // Epilogue. c fragment: (row=lane/4, col=(lane%4)*2) and (+8 row) per tile.
    const int row = lane >> 2;
    const int col = (lane & 3) * 2;
    const int gr0 = m0 + mw + row;
    const int gc0 = n0 + nw + col;
    const float c00 = Cs[nw + col], c01 = Cs[nw + col + 1];
    const float c10 = Cs[nw + col + 8], c11 = Cs[nw + col + 9];
    float2* o;
    o = (float2*)(out + (size_t)gr0 * K_ + gc0);
    *o = make_float2(acc0[0] + c00, acc0[1] + c01);
    o = (float2*)(out + (size_t)(gr0 + 8) * K_ + gc0);
    *o = make_float2(acc0[2] + c00, acc0[3] + c01);
    o = (float2*)(out + (size_t)gr0 * K_ + gc0 + 8);
    *o = make_float2(acc1[0] + c10, acc1[1] + c11);
    o = (float2*)(out + (size_t)(gr0 + 8) * K_ + gc0 + 8);
    *o = make_float2(acc1[2] + c10, acc1[3] + c11);
}

// ---------------------------------------------------------------------------
extern "C" void kernel_launch(void* const* d_in, const int* in_sizes, int n_in,
                              void* d_out, int out_size) {
    const float* x     = (const float*)d_in[0];
    const float* means = (const float*)d_in[1];
    const float* rho   = (const float*)d_in[2];
    float* out = (float*)d_out;

    cudaFuncSetAttribute(gemm_kernel, cudaFuncAttributeMaxDynamicSharedMemorySize,
                         2 * STAGE_BYTES);

    prep_kernel<<<NB_U + 32, 256>>>(x, means, rho);
    gemm_kernel<<<dim3(B_ / BM, K_ / BN), 256, 2 * STAGE_BYTES>>>(out);
}